// round 1
// baseline (speedup 1.0000x reference)
#include <cuda_runtime.h>
#include <cstdint>

// FPSampler: farthest point sampling, B=16, N=131072, npoint=1024.
// 16 batch groups x 8 CTAs, 512 threads/CTA, one CTA per SM (single wave).
// xyz planes resident in 192KB SMEM per CTA, distances in registers.
// Per-group sync via monotonic L2 counter + double-buffered candidate slots.

#define BB 16
#define NN 131072
#define NP 1024
#define GG 8                     // CTAs per batch group
#define PTS (NN / GG)            // 16384 points per CTA
#define NT 512                   // threads per CTA
#define KK (PTS / NT)            // 32 points per thread
#define GRID (BB * GG)           // 128 CTAs
#define SMEM_BYTES (3 * PTS * sizeof(float))

struct Slot {
    unsigned long long pk;       // (float_bits(bestv) << 32) | (0xFFFFFFFF - idx)
    float x, y, z;
    unsigned pad;
};

__device__ Slot g_slots[2][BB][GG];
__device__ unsigned g_cnt[BB * 32];   // one counter per group, spread across lines

struct StartArg { int s[BB]; };

__global__ void fps_init_kernel() {
    int i = threadIdx.x;
    if (i < BB) g_cnt[i * 32] = 0u;
}

__global__ void __launch_bounds__(NT, 1)
fps_main_kernel(const float* __restrict__ xyz, float* __restrict__ out, StartArg st)
{
    extern __shared__ float smem[];
    float* xs = smem;
    float* ys = smem + PTS;
    float* zs = smem + 2 * PTS;
    __shared__ unsigned long long wred[NT / 32];
    __shared__ float bc[3];

    const int cta  = blockIdx.x;
    const int b    = cta >> 3;       // batch (GG == 8)
    const int c    = cta & 7;        // CTA within group
    const int t    = threadIdx.x;
    const int lane = t & 31;
    const int warp = t >> 5;
    const int base = c * PTS;        // first global point index of this CTA

    const float* xb = xyz + (size_t)b * NN * 3;
    float* out_xyz = out;
    float* out_idx = out + (size_t)BB * NP * 3;

    // One-time load of this CTA's point slab into SMEM planes.
    for (int p = t; p < PTS; p += NT) {
        const float* src = xb + (size_t)(base + p) * 3;
        xs[p] = src[0];
        ys[p] = src[1];
        zs[p] = src[2];
    }

    float dist[KK];
#pragma unroll
    for (int k = 0; k < KK; k++) dist[k] = 1e10f;   // INF from reference

    // First centroid = start[b] (read broadcast from gmem).
    const int fi = st.s[b];
    float cx = xb[(size_t)fi * 3 + 0];
    float cy = xb[(size_t)fi * 3 + 1];
    float cz = xb[(size_t)fi * 3 + 2];

    if (c == 0 && t == 0) {
        size_t o3 = (size_t)b * NP * 3;
        out_xyz[o3 + 0] = cx;
        out_xyz[o3 + 1] = cy;
        out_xyz[o3 + 2] = cz;
        out_idx[(size_t)b * NP] = (float)fi;
    }
    __syncthreads();

    for (int it = 1; it < NP; it++) {
        // ---- distance update + local argmax (first-index semantics) ----
        float bestv = -1.0f;
        int bestp = 0;
#pragma unroll
        for (int k = 0; k < KK; k++) {
            int p = t + k * NT;                 // ascending global index per thread
            float dx = xs[p] - cx;
            float dy = ys[p] - cy;
            float dz = zs[p] - cz;
            // exact reference order: (dx*dx + dy*dy) + dz*dz, no FMA contraction
            float d = __fadd_rn(__fadd_rn(__fmul_rn(dx, dx), __fmul_rn(dy, dy)),
                                __fmul_rn(dz, dz));
            float nd = fminf(dist[k], d);
            dist[k] = nd;
            if (nd > bestv) { bestv = nd; bestp = p; }   // strict > keeps lowest index
        }
        unsigned gidx = (unsigned)(base + bestp);
        // distances are >= 0, so float bits are monotone as unsigned.
        unsigned long long pk =
            ((unsigned long long)__float_as_uint(bestv) << 32) |
            (unsigned)(0xFFFFFFFFu - gidx);              // tie -> smaller index wins

        // ---- warp reduce ----
#pragma unroll
        for (int off = 16; off > 0; off >>= 1) {
            unsigned long long o = __shfl_xor_sync(0xFFFFFFFFu, pk, off);
            if (o > pk) pk = o;
        }
        if (lane == 0) wred[warp] = pk;
        __syncthreads();

        // ---- CTA reduce + group exchange (warp 0) ----
        if (warp == 0) {
            unsigned long long p2 = (lane < (NT / 32)) ? wred[lane] : 0ull;
#pragma unroll
            for (int off = 8; off > 0; off >>= 1) {
                unsigned long long o = __shfl_xor_sync(0xFFFFFFFFu, p2, off);
                if (o > p2) p2 = o;
            }
            if (lane == 0) {
                unsigned gw = 0xFFFFFFFFu - (unsigned)(p2 & 0xFFFFFFFFull);
                int lp = (int)gw - base;                  // CTA-local winner
                Slot* sl = &g_slots[it & 1][b][c];
                sl->pk = p2;
                sl->x = xs[lp];
                sl->y = ys[lp];
                sl->z = zs[lp];
                __threadfence();                          // publish slot before arrive
                atomicAdd(&g_cnt[b * 32], 1u);

                const unsigned target = (unsigned)(GG * it);
                volatile unsigned* cp = &g_cnt[b * 32];
                while (*cp < target) __nanosleep(64);
                __threadfence();                          // acquire

                unsigned long long pks[GG];
#pragma unroll
                for (int j = 0; j < GG; j++)
                    pks[j] = __ldcg(&g_slots[it & 1][b][j].pk);
                unsigned long long wb = 0ull; int wc = 0;
#pragma unroll
                for (int j = 0; j < GG; j++)
                    if (pks[j] > wb) { wb = pks[j]; wc = j; }

                float wx = __ldcg(&g_slots[it & 1][b][wc].x);
                float wy = __ldcg(&g_slots[it & 1][b][wc].y);
                float wz = __ldcg(&g_slots[it & 1][b][wc].z);
                unsigned widx = 0xFFFFFFFFu - (unsigned)(wb & 0xFFFFFFFFull);
                bc[0] = wx; bc[1] = wy; bc[2] = wz;

                if (c == 0) {
                    size_t o3 = ((size_t)b * NP + it) * 3;
                    out_xyz[o3 + 0] = wx;
                    out_xyz[o3 + 1] = wy;
                    out_xyz[o3 + 2] = wz;
                    out_idx[(size_t)b * NP + it] = (float)widx;
                }
            }
        }
        __syncthreads();
        cx = bc[0]; cy = bc[1]; cz = bc[2];
    }
}

// ---------------------------------------------------------------------------
// Host-side reproduction of JAX Threefry RNG for `start`:
//   start = randint(fold_in(key(0), 1), (16,), 0, 131072)
// Assumes jax_threefry_partitionable=True (modern JAX default):
//   split keys  = threefry2x32(K, (0,0)) and (0,1)
//   random_bits = out0 ^ out1 at counters (0, b)
//   span = 2^17 (power of two) => multiplier term vanishes, start = bits & 0x1FFFF
// ---------------------------------------------------------------------------
static void tf2x32(uint32_t k0, uint32_t k1, uint32_t c0, uint32_t c1,
                   uint32_t* o0, uint32_t* o1)
{
    uint32_t ks[3] = { k0, k1, k0 ^ k1 ^ 0x1BD11BDAu };
    uint32_t x0 = c0 + ks[0];
    uint32_t x1 = c1 + ks[1];
    static const int rot[2][4] = { {13, 15, 26, 6}, {17, 29, 16, 24} };
    for (int i = 0; i < 5; i++) {
        const int* r = rot[i & 1];
        for (int j = 0; j < 4; j++) {
            x0 += x1;
            x1 = (x1 << r[j]) | (x1 >> (32 - r[j]));
            x1 ^= x0;
        }
        x0 += ks[(i + 1) % 3];
        x1 += ks[(i + 2) % 3] + (uint32_t)(i + 1);
    }
    *o0 = x0;
    *o1 = x1;
}

static void compute_start(int* s)
{
    // fold_in(key(0)=[0,0], data=1): counter (0,1)
    uint32_t K0, K1;
    tf2x32(0u, 0u, 0u, 1u, &K0, &K1);
    // partitionable split: k2 (lower-bits key) = full output at counter (0,1)
    uint32_t b0, b1;
    tf2x32(K0, K1, 0u, 1u, &b0, &b1);
    for (int i = 0; i < BB; i++) {
        uint32_t y0, y1;
        tf2x32(b0, b1, 0u, (uint32_t)i, &y0, &y1);
        s[i] = (int)((y0 ^ y1) & (uint32_t)(NN - 1));   // span = 2^17
    }
}

extern "C" void kernel_launch(void* const* d_in, const int* in_sizes, int n_in,
                              void* d_out, int out_size)
{
    const float* xyz = (const float*)d_in[0];
    float* out = (float*)d_out;

    StartArg st;
    compute_start(st.s);

    cudaFuncSetAttribute(fps_main_kernel,
                         cudaFuncAttributeMaxDynamicSharedMemorySize,
                         (int)SMEM_BYTES);

    fps_init_kernel<<<1, 32>>>();
    fps_main_kernel<<<GRID, NT, SMEM_BYTES>>>(xyz, out, st);
}